// round 17
// baseline (speedup 1.0000x reference)
#include <cuda_runtime.h>

#define IMG     512
#define KW      33
#define HBLK    128
#define WBLK    128
#define PATCH_H 36
#define PATCH_W 160
#define PSTRIDE 168                      // words/patch row; 42x16B granules, 42 mod 8 == 2 -> conflict-free LDS.128
#define CSTRIDE (PATCH_H * PSTRIDE)      // 6048 words per channel
#define WBC     32                       // kernel-blocks per CTA (x)
#define NG      4                        // u-split groups (9+8+8+8 = 33)
#define KROW    36                       // padded v-stride (33 -> 36; 144B, 16B aligned)
#define KSEG    (WBC * KROW)             // 1152 words per group segment
#define KBUF_WORDS (NG * KSEG)           // 4608 words per buffer
#define SMEM_WORDS (3 * CSTRIDE + 2 * KBUF_WORDS)
#define SMEM_BYTES (SMEM_WORDS * 4)      // 109,440 B -> 2 CTAs/SM, 32 warps/SM (R10-verified footprint)

__device__ __forceinline__ unsigned smem_u32(const void* p) {
    unsigned a;
    asm("{ .reg .u64 t; cvta.to.shared.u64 t, %1; cvt.u32.u64 %0, t; }" : "=r"(a) : "l"(p));
    return a;
}

__global__ __launch_bounds__(512, 2)
void reblur_kernel(const float* __restrict__ img,
                   const float* __restrict__ Kg,
                   float* __restrict__ out)
{
    extern __shared__ float smem[];
    float* patchS = smem;                      // [3][36][PSTRIDE]
    float* Ksm0   = smem + 3 * CSTRIDE;        // [NG][WBC][KROW]
    float* Ksm1   = Ksm0 + KBUF_WORDS;

    const int tid    = threadIdx.x;
    const int g      = tid >> 7;        // u-group 0..3 (4 warps each)
    const int wg_tid = tid & 127;
    const int oi     = wg_tid & 3;
    const int wbc    = wg_tid >> 2;     // 0..31
    const int warp   = tid >> 5;        // 0..15
    const int lane   = tid & 31;
    const int bx     = blockIdx.x;      // 0..3
    const int hb     = blockIdx.y;      // 0..127

    const int ulen = (g == 0) ? 9 : 8;             // private iteration count
    const int uoff = (g == 0) ? 0 : (8 * g + 1);   // 0,9,17,25

    // -------- patch staging: 108 (c,row) jobs over 16 warps, divide-free-ish, cp.async --------
    const int col0 = 128 * bx - 16;
    const int row0 = 4 * hb - 16;
    #pragma unroll
    for (int j = 0; j < 7; ++j) {
        int rj = warp + 16 * j;                    // 0..108
        if (rj < 3 * PATCH_H) {
            int c = (rj * 57) >> 11;               // rj/36 for rj<108 (57/2048 trick), exact
            int r = rj - 36 * c;
            int ri = min(max(row0 + r, 0), IMG - 1);       // 'edge' pad
            const float* srow = img + (c * IMG + ri) * IMG;
            unsigned drow = smem_u32(patchS) + 4u * (unsigned)(c * CSTRIDE + r * PSTRIDE);
            #pragma unroll
            for (int q = 0; q < 5; ++q) {
                int x  = lane + 32 * q;
                int ci = min(max(col0 + x, 0), IMG - 1);
                asm volatile("cp.async.ca.shared.global [%0], [%1], 4;"
                             :: "r"(drow + 4u * (unsigned)x), "l"(srow + ci));
            }
        }
    }
    asm volatile("cp.async.commit_group;" ::: "memory");

    // ------- per-group K staging: group g stages ONLY row u = uoff + t into its segment -------
    const float* Kpix = Kg + hb * WBLK + WBC * bx;     // + (u*KW+v)*HBLK*WBLK + wb
    auto stageg = [&](float* dstbuf, int t) {
        const float* Ksrc = Kpix + (size_t)(uoff + t) * KW * (HBLK * WBLK);
        unsigned dbase = smem_u32(dstbuf) + 4u * (unsigned)(g * KSEG);
        #pragma unroll
        for (int j = 0; j < 9; ++j) {
            int idx = wg_tid + 128 * j;
            if (j < 8 || idx < KW * WBC) {                 // last iter: only wg_tid < 32
                int v  = idx >> 5;
                int wb = idx & 31;
                const float* src = Ksrc + (size_t)v * (HBLK * WBLK) + wb;
                unsigned dst = dbase + 4u * (unsigned)(wb * KROW + v);
                asm volatile("cp.async.ca.shared.global [%0], [%1], 4;" :: "r"(dst), "l"(src));
            }
        }
        asm volatile("cp.async.commit_group;" ::: "memory");
    };

    stageg(Ksm0, 0);
    asm volatile("cp.async.wait_group 0;" ::: "memory");   // waits patch + own K0
    __syncthreads();                                        // global: patch written by all

    // ---------------- main compute: ulen private steps, thirds tiling (12/12/9) ----------------
    float acc[3][4];
    #pragma unroll
    for (int c = 0; c < 3; ++c)
        #pragma unroll
        for (int j = 0; j < 4; ++j) acc[c][j] = 0.f;

    const unsigned bar_id = (unsigned)(g + 1);     // named barriers 1..4, 128 threads each

    #pragma unroll 1
    for (int t = 0; t < ulen; ++t) {
        float* cur = (t & 1) ? Ksm1 : Ksm0;
        float* nxt = (t & 1) ? Ksm0 : Ksm1;
        if (t + 1 < ulen) stageg(nxt, t + 1);     // overlap next row's HBM loads

        const float* krow = cur + g * KSEG + wbc * KROW;
        const float* prow = patchS + (oi + uoff + t) * PSTRIDE + 4 * wbc;

        // ---- third 0: v in [0,12), p[0..15] ----
        {
            float kk[12];
            const float4* ks = reinterpret_cast<const float4*>(krow);
            #pragma unroll
            for (int j = 0; j < 3; ++j) {
                float4 v4 = ks[j];
                kk[4*j] = v4.x; kk[4*j+1] = v4.y; kk[4*j+2] = v4.z; kk[4*j+3] = v4.w;
            }
            #pragma unroll
            for (int c = 0; c < 3; ++c) {
                float p[16];
                const float4* ps = reinterpret_cast<const float4*>(prow + c * CSTRIDE);
                #pragma unroll
                for (int j = 0; j < 4; ++j) {
                    float4 v4 = ps[j];
                    p[4*j] = v4.x; p[4*j+1] = v4.y; p[4*j+2] = v4.z; p[4*j+3] = v4.w;
                }
                float a0 = acc[c][0], a1 = acc[c][1], a2 = acc[c][2], a3 = acc[c][3];
                #pragma unroll
                for (int v = 0; v < 12; ++v) {
                    float kv = kk[v];
                    a0 = fmaf(kv, p[v],     a0);
                    a1 = fmaf(kv, p[v + 1], a1);
                    a2 = fmaf(kv, p[v + 2], a2);
                    a3 = fmaf(kv, p[v + 3], a3);
                }
                acc[c][0] = a0; acc[c][1] = a1; acc[c][2] = a2; acc[c][3] = a3;
            }
        }
        // ---- third 1: v in [12,24), p[12..27] ----
        {
            float kk[12];
            const float4* ks = reinterpret_cast<const float4*>(krow + 12);
            #pragma unroll
            for (int j = 0; j < 3; ++j) {
                float4 v4 = ks[j];
                kk[4*j] = v4.x; kk[4*j+1] = v4.y; kk[4*j+2] = v4.z; kk[4*j+3] = v4.w;
            }
            #pragma unroll
            for (int c = 0; c < 3; ++c) {
                float p[16];
                const float4* ps = reinterpret_cast<const float4*>(prow + c * CSTRIDE + 12);
                #pragma unroll
                for (int j = 0; j < 4; ++j) {
                    float4 v4 = ps[j];
                    p[4*j] = v4.x; p[4*j+1] = v4.y; p[4*j+2] = v4.z; p[4*j+3] = v4.w;
                }
                float a0 = acc[c][0], a1 = acc[c][1], a2 = acc[c][2], a3 = acc[c][3];
                #pragma unroll
                for (int v = 0; v < 12; ++v) {
                    float kv = kk[v];
                    a0 = fmaf(kv, p[v],     a0);
                    a1 = fmaf(kv, p[v + 1], a1);
                    a2 = fmaf(kv, p[v + 2], a2);
                    a3 = fmaf(kv, p[v + 3], a3);
                }
                acc[c][0] = a0; acc[c][1] = a1; acc[c][2] = a2; acc[c][3] = a3;
            }
        }
        // ---- third 2: v in [24,33), p[24..35] ----
        {
            float kk[12];                              // kk[9..11] = pads, unused
            const float4* ks = reinterpret_cast<const float4*>(krow + 24);
            #pragma unroll
            for (int j = 0; j < 3; ++j) {
                float4 v4 = ks[j];
                kk[4*j] = v4.x; kk[4*j+1] = v4.y; kk[4*j+2] = v4.z; kk[4*j+3] = v4.w;
            }
            #pragma unroll
            for (int c = 0; c < 3; ++c) {
                float p[12];
                const float4* ps = reinterpret_cast<const float4*>(prow + c * CSTRIDE + 24);
                #pragma unroll
                for (int j = 0; j < 3; ++j) {
                    float4 v4 = ps[j];
                    p[4*j] = v4.x; p[4*j+1] = v4.y; p[4*j+2] = v4.z; p[4*j+3] = v4.w;
                }
                float a0 = acc[c][0], a1 = acc[c][1], a2 = acc[c][2], a3 = acc[c][3];
                #pragma unroll
                for (int v = 0; v < 9; ++v) {
                    float kv = kk[v];
                    a0 = fmaf(kv, p[v],     a0);
                    a1 = fmaf(kv, p[v + 1], a1);
                    a2 = fmaf(kv, p[v + 2], a2);
                    a3 = fmaf(kv, p[v + 3], a3);
                }
                acc[c][0] = a0; acc[c][1] = a1; acc[c][2] = a2; acc[c][3] = a3;
            }
        }

        // Drain own K_{t+1}; sync ONLY this group's 4 warps (segment is group-private).
        asm volatile("cp.async.wait_group 0;" ::: "memory");
        asm volatile("bar.sync %0, %1;" :: "r"(bar_id), "r"(128) : "memory");
    }

    // ---------------- 4-way reduction through smem (reuse patch region) ----------------
    float* red = patchS;   // 3*128*12 = 4608 words << patch
    __syncthreads();       // global: all groups done; patch no longer needed
    if (g > 0) {
        float* dst = red + ((g - 1) * 128 + wg_tid) * 12;
        #pragma unroll
        for (int c = 0; c < 3; ++c)
            #pragma unroll
            for (int j = 0; j < 4; ++j) dst[c * 4 + j] = acc[c][j];
    }
    __syncthreads();

    if (g == 0) {
        const float* p1 = red + wg_tid * 12;
        const float* p2 = red + (128 + wg_tid) * 12;
        const float* p3 = red + (256 + wg_tid) * 12;
        const int orow = 4 * hb + oi;
        const int ocol = 128 * bx + 4 * wbc;
        #pragma unroll
        for (int c = 0; c < 3; ++c) {
            float4 r;
            r.x = acc[c][0] + (p1[c*4+0] + p2[c*4+0]) + p3[c*4+0];
            r.y = acc[c][1] + (p1[c*4+1] + p2[c*4+1]) + p3[c*4+1];
            r.z = acc[c][2] + (p1[c*4+2] + p2[c*4+2]) + p3[c*4+2];
            r.w = acc[c][3] + (p1[c*4+3] + p2[c*4+3]) + p3[c*4+3];
            *reinterpret_cast<float4*>(out + (c * IMG + orow) * IMG + ocol) = r;
        }
    }
}

extern "C" void kernel_launch(void* const* d_in, const int* in_sizes, int n_in,
                              void* d_out, int out_size)
{
    const float* img = (const float*)d_in[0];   // (1,3,512,512) fp32
    const float* Kg  = (const float*)d_in[1];   // (1,1089,128,128) fp32
    float* out = (float*)d_out;                 // (1,3,512,512) fp32

    cudaFuncSetAttribute(reblur_kernel,
                         cudaFuncAttributeMaxDynamicSharedMemorySize, SMEM_BYTES);
    dim3 grid(4, 128);
    reblur_kernel<<<grid, 512, SMEM_BYTES>>>(img, Kg, out);
}